// round 9
// baseline (speedup 1.0000x reference)
#include <cuda_runtime.h>
#include <cstdint>

// VoxelHashTable: out[i] = voxel_features[table[hash(floor(q_i/0.1))]] or 0.
//
// R5: same two-phase clustering as R4 (bin queries by vidx>>7 so repeated /
// nearby rows hit L2 in the copy phase), but the scatter is now atomic-free:
// pass1 takes the per-bin rank (atomic folded into its memory-latency slack),
// scatter becomes a pure computed write. R4's k_scatter burned 18.7us on
// contended ATOMG latency (issue=1.1%).

#define FDIM4       192u            // 768/4 float4 per row
#define TABLE_MASK  0xFFFFFu        // 2^20 - 1
#define MAXM        (1 << 18)       // 262144 queries
#define NBINS       4096
#define BIN_SHIFT   7               // bin = vidx >> 7  (128 rows = 393KB per bin)

__device__ int g_table_is_i32;
__device__ int g_vidx[MAXM];        // per-query voxel index (-1 = invalid)
__device__ int g_rank[MAXM];        // per-query rank within its bin
__device__ int g_perm[MAXM];        // query ids sorted by bin
__device__ int g_hist[NBINS];
__device__ int g_offs[NBINS];

// ---- kernel 1: zero histogram + detect table dtype (1 block) --------------
// int64 table => every odd 32-bit word is 0x0 or 0xFFFFFFFF. int32 table =>
// ~24% of words are live indices, so 512 sampled words give certainty.
__global__ void k_init_detect(const unsigned* __restrict__ tbl_words)
{
    int t = threadIdx.x;                       // 1024 threads
    #pragma unroll
    for (int i = 0; i < NBINS / 1024; i++)
        g_hist[t + i * 1024] = 0;

    __shared__ int found;
    if (t == 0) found = 0;
    __syncthreads();
    if (t < 512) {
        unsigned w = tbl_words[2 * t + 1];
        if (w != 0u && w != 0xFFFFFFFFu) found = 1;
    }
    __syncthreads();
    if (t == 0) g_table_is_i32 = found;
}

// ---- kernel 2: hash + table lookup + histogram + per-bin rank -------------
__global__ __launch_bounds__(256) void k_pass1(
    const float* __restrict__ query_pts,
    const int*       __restrict__ table32,
    const long long* __restrict__ table64,
    int M, int V)
{
    int i = blockIdx.x * blockDim.x + threadIdx.x;
    if (i >= M) return;

    const float* qp = query_pts + 3ull * (unsigned)i;
    float x = __ldg(qp + 0);
    float y = __ldg(qp + 1);
    float z = __ldg(qp + 2);

    // bit-exact replica of jnp.floor(q / 0.1f): IEEE-RN fp32 division
    int gx = __float2int_rd(__fdiv_rn(x, 0.1f));
    int gy = __float2int_rd(__fdiv_rn(y, 0.1f));
    int gz = __float2int_rd(__fdiv_rn(z, 0.1f));

    // int64 (sum mod 2^20) == uint32 wraparound sum & (2^20-1): 2^20 | 2^32
    unsigned h = ((unsigned)gx * 73856093u
                + (unsigned)gy * 19349669u
                + (unsigned)gz * 83492791u) & TABLE_MASK;

    long long v;
    if (g_table_is_i32) v = (long long)__ldg(table32 + h);
    else                v = __ldg(table64 + h);

    int vidx = (v >= 0 && v < (long long)V) ? (int)v : -1;
    g_vidx[i] = vidx;

    int bin = (vidx < 0) ? 0 : (vidx >> BIN_SHIFT);
    // rank within bin; atomic latency hides behind this kernel's table/query
    // loads instead of standing alone like R4's scatter did.
    g_rank[i] = atomicAdd(&g_hist[bin], 1);
}

// ---- kernel 3: exclusive prefix scan over NBINS (1 block, 1024 thr) -------
__global__ void k_scan()
{
    __shared__ int s[1024];
    int t = threadIdx.x;
    const int PER = NBINS / 1024;              // 4

    int local[PER];
    int sum = 0;
    #pragma unroll
    for (int i = 0; i < PER; i++) { local[i] = g_hist[t * PER + i]; sum += local[i]; }
    s[t] = sum;
    __syncthreads();

    #pragma unroll
    for (int d = 1; d < 1024; d <<= 1) {
        int v = (t >= d) ? s[t - d] : 0;
        __syncthreads();
        s[t] += v;
        __syncthreads();
    }
    int base = s[t] - sum;                     // exclusive prefix of this thread
    #pragma unroll
    for (int i = 0; i < PER; i++) { g_offs[t * PER + i] = base; base += local[i]; }
}

// ---- kernel 4: atomic-free scatter ----------------------------------------
__global__ __launch_bounds__(256) void k_scatter(int M)
{
    int i = blockIdx.x * blockDim.x + threadIdx.x;
    if (i >= M) return;
    int vidx = g_vidx[i];
    int bin  = (vidx < 0) ? 0 : (vidx >> BIN_SHIFT);
    g_perm[g_offs[bin] + g_rank[i]] = i;
}

// ---- kernel 5: main copy, warp per query in clustered order ---------------
__global__ __launch_bounds__(256) void k_copy(
    const float4* __restrict__ feats,
    float4* __restrict__ out,
    int M)
{
    const int slot = (int)((blockIdx.x * blockDim.x + threadIdx.x) >> 5);
    const int lane = threadIdx.x & 31;
    if (slot >= M) return;

    const int qid  = g_perm[slot];
    const int vidx = g_vidx[qid];

    float4* dst = out + (size_t)(unsigned)qid * FDIM4;

    if (vidx >= 0) {
        const float4* src = feats + (size_t)(unsigned)vidx * FDIM4;
        float4 v0 = __ldg(src + lane + 0 * 32);
        float4 v1 = __ldg(src + lane + 1 * 32);
        float4 v2 = __ldg(src + lane + 2 * 32);
        float4 v3 = __ldg(src + lane + 3 * 32);
        float4 v4 = __ldg(src + lane + 4 * 32);
        float4 v5 = __ldg(src + lane + 5 * 32);
        __stwt(dst + lane + 0 * 32, v0);
        __stwt(dst + lane + 1 * 32, v1);
        __stwt(dst + lane + 2 * 32, v2);
        __stwt(dst + lane + 3 * 32, v3);
        __stwt(dst + lane + 4 * 32, v4);
        __stwt(dst + lane + 5 * 32, v5);
    } else {
        const float4 z4 = make_float4(0.f, 0.f, 0.f, 0.f);
        #pragma unroll
        for (int i = 0; i < 6; i++)
            __stwt(dst + lane + i * 32, z4);
    }
}

// ---- fallback: single-kernel path (if M exceeds scratch) ------------------
__global__ __launch_bounds__(256) void k_direct(
    const float* __restrict__ query_pts,
    const float4* __restrict__ feats,
    const int*       __restrict__ table32,
    const long long* __restrict__ table64,
    float4* __restrict__ out,
    int M, int V)
{
    const int gwarp = (int)((blockIdx.x * blockDim.x + threadIdx.x) >> 5);
    const int lane  = threadIdx.x & 31;
    if (gwarp >= M) return;

    const float* qp = query_pts + 3ull * (unsigned)gwarp;
    int gx = __float2int_rd(__fdiv_rn(__ldg(qp + 0), 0.1f));
    int gy = __float2int_rd(__fdiv_rn(__ldg(qp + 1), 0.1f));
    int gz = __float2int_rd(__fdiv_rn(__ldg(qp + 2), 0.1f));
    unsigned h = ((unsigned)gx * 73856093u + (unsigned)gy * 19349669u
                + (unsigned)gz * 83492791u) & TABLE_MASK;

    long long vidx;
    if (g_table_is_i32) vidx = (long long)__ldg(table32 + h);
    else                vidx = __ldg(table64 + h);

    float4* dst = out + (size_t)gwarp * FDIM4;
    if (vidx >= 0 && vidx < (long long)V) {
        const float4* src = feats + (size_t)vidx * FDIM4;
        #pragma unroll
        for (int i = 0; i < 6; i++)
            __stwt(dst + lane + i * 32, __ldg(src + lane + i * 32));
    } else {
        const float4 z4 = make_float4(0.f, 0.f, 0.f, 0.f);
        #pragma unroll
        for (int i = 0; i < 6; i++)
            __stwt(dst + lane + i * 32, z4);
    }
}

extern "C" void kernel_launch(void* const* d_in, const int* in_sizes, int n_in,
                              void* d_out, int out_size)
{
    // ---- resolve input roles by element count ----
    int i_feat = 0;
    for (int i = 1; i < n_in; i++)
        if ((long long)in_sizes[i] > (long long)in_sizes[i_feat]) i_feat = i;

    int i_table = -1, i_query = -1;
    for (int i = 0; i < n_in; i++) {
        if (i == i_feat) continue;
        if (in_sizes[i] == (1 << 20)) i_table = i;
        else                          i_query = i;
    }
    if (i_table < 0 || i_query < 0) { i_query = 0; i_feat = 1; i_table = 2; }

    const float*     q     = (const float*)d_in[i_query];
    const float4*    feats = (const float4*)d_in[i_feat];
    const int*       t32   = (const int*)d_in[i_table];
    const long long* t64   = (const long long*)d_in[i_table];
    float4*          out   = (float4*)d_out;

    const int M = in_sizes[i_query] / 3;
    const int V = in_sizes[i_feat] / 768;

    k_init_detect<<<1, 1024>>>((const unsigned*)d_in[i_table]);

    if (M <= MAXM) {
        const int tpb = 256;
        k_pass1  <<<(M + tpb - 1) / tpb, tpb>>>(q, t32, t64, M, V);
        k_scan   <<<1, 1024>>>();
        k_scatter<<<(M + tpb - 1) / tpb, tpb>>>(M);
        const int blocks = (M * 32 + tpb - 1) / tpb;      // warp per query
        k_copy   <<<blocks, tpb>>>(feats, out, M);
    } else {
        const int blocks = (M * 32 + 255) / 256;
        k_direct<<<blocks, 256>>>(q, feats, t32, t64, out, M, V);
    }
}

// round 10
// speedup vs baseline: 1.0065x; 1.0065x over previous
#include <cuda_runtime.h>
#include <cstdint>

// VoxelHashTable: out[i] = voxel_features[table[hash(floor(q_i/0.1))]] or 0.
//
// R5: same two-phase clustering as R4 (bin queries by vidx>>7 so repeated /
// nearby rows hit L2 in the copy phase), but the scatter is now atomic-free:
// pass1 takes the per-bin rank (atomic folded into its memory-latency slack),
// scatter becomes a pure computed write. R4's k_scatter burned 18.7us on
// contended ATOMG latency (issue=1.1%).

#define FDIM4       192u            // 768/4 float4 per row
#define TABLE_MASK  0xFFFFFu        // 2^20 - 1
#define MAXM        (1 << 18)       // 262144 queries
#define NBINS       4096
#define BIN_SHIFT   7               // bin = vidx >> 7  (128 rows = 393KB per bin)

__device__ int g_table_is_i32;
__device__ int g_vidx[MAXM];        // per-query voxel index (-1 = invalid)
__device__ int g_rank[MAXM];        // per-query rank within its bin
__device__ int g_perm[MAXM];        // query ids sorted by bin
__device__ int g_hist[NBINS];
__device__ int g_offs[NBINS];

// ---- kernel 1: zero histogram + detect table dtype (1 block) --------------
// int64 table => every odd 32-bit word is 0x0 or 0xFFFFFFFF. int32 table =>
// ~24% of words are live indices, so 512 sampled words give certainty.
__global__ void k_init_detect(const unsigned* __restrict__ tbl_words)
{
    int t = threadIdx.x;                       // 1024 threads
    #pragma unroll
    for (int i = 0; i < NBINS / 1024; i++)
        g_hist[t + i * 1024] = 0;

    __shared__ int found;
    if (t == 0) found = 0;
    __syncthreads();
    if (t < 512) {
        unsigned w = tbl_words[2 * t + 1];
        if (w != 0u && w != 0xFFFFFFFFu) found = 1;
    }
    __syncthreads();
    if (t == 0) g_table_is_i32 = found;
}

// ---- kernel 2: hash + table lookup + histogram + per-bin rank -------------
__global__ __launch_bounds__(256) void k_pass1(
    const float* __restrict__ query_pts,
    const int*       __restrict__ table32,
    const long long* __restrict__ table64,
    int M, int V)
{
    int i = blockIdx.x * blockDim.x + threadIdx.x;
    if (i >= M) return;

    const float* qp = query_pts + 3ull * (unsigned)i;
    float x = __ldg(qp + 0);
    float y = __ldg(qp + 1);
    float z = __ldg(qp + 2);

    // bit-exact replica of jnp.floor(q / 0.1f): IEEE-RN fp32 division
    int gx = __float2int_rd(__fdiv_rn(x, 0.1f));
    int gy = __float2int_rd(__fdiv_rn(y, 0.1f));
    int gz = __float2int_rd(__fdiv_rn(z, 0.1f));

    // int64 (sum mod 2^20) == uint32 wraparound sum & (2^20-1): 2^20 | 2^32
    unsigned h = ((unsigned)gx * 73856093u
                + (unsigned)gy * 19349669u
                + (unsigned)gz * 83492791u) & TABLE_MASK;

    long long v;
    if (g_table_is_i32) v = (long long)__ldg(table32 + h);
    else                v = __ldg(table64 + h);

    int vidx = (v >= 0 && v < (long long)V) ? (int)v : -1;
    g_vidx[i] = vidx;

    int bin = (vidx < 0) ? 0 : (vidx >> BIN_SHIFT);
    // rank within bin; atomic latency hides behind this kernel's table/query
    // loads instead of standing alone like R4's scatter did.
    g_rank[i] = atomicAdd(&g_hist[bin], 1);
}

// ---- kernel 3: exclusive prefix scan over NBINS (1 block, 1024 thr) -------
__global__ void k_scan()
{
    __shared__ int s[1024];
    int t = threadIdx.x;
    const int PER = NBINS / 1024;              // 4

    int local[PER];
    int sum = 0;
    #pragma unroll
    for (int i = 0; i < PER; i++) { local[i] = g_hist[t * PER + i]; sum += local[i]; }
    s[t] = sum;
    __syncthreads();

    #pragma unroll
    for (int d = 1; d < 1024; d <<= 1) {
        int v = (t >= d) ? s[t - d] : 0;
        __syncthreads();
        s[t] += v;
        __syncthreads();
    }
    int base = s[t] - sum;                     // exclusive prefix of this thread
    #pragma unroll
    for (int i = 0; i < PER; i++) { g_offs[t * PER + i] = base; base += local[i]; }
}

// ---- kernel 4: atomic-free scatter ----------------------------------------
__global__ __launch_bounds__(256) void k_scatter(int M)
{
    int i = blockIdx.x * blockDim.x + threadIdx.x;
    if (i >= M) return;
    int vidx = g_vidx[i];
    int bin  = (vidx < 0) ? 0 : (vidx >> BIN_SHIFT);
    g_perm[g_offs[bin] + g_rank[i]] = i;
}

// ---- kernel 5: main copy, warp per query in clustered order ---------------
__global__ __launch_bounds__(256) void k_copy(
    const float4* __restrict__ feats,
    float4* __restrict__ out,
    int M)
{
    const int slot = (int)((blockIdx.x * blockDim.x + threadIdx.x) >> 5);
    const int lane = threadIdx.x & 31;
    if (slot >= M) return;

    const int qid  = g_perm[slot];
    const int vidx = g_vidx[qid];

    float4* dst = out + (size_t)(unsigned)qid * FDIM4;

    if (vidx >= 0) {
        const float4* src = feats + (size_t)(unsigned)vidx * FDIM4;
        float4 v0 = __ldg(src + lane + 0 * 32);
        float4 v1 = __ldg(src + lane + 1 * 32);
        float4 v2 = __ldg(src + lane + 2 * 32);
        float4 v3 = __ldg(src + lane + 3 * 32);
        float4 v4 = __ldg(src + lane + 4 * 32);
        float4 v5 = __ldg(src + lane + 5 * 32);
        __stwt(dst + lane + 0 * 32, v0);
        __stwt(dst + lane + 1 * 32, v1);
        __stwt(dst + lane + 2 * 32, v2);
        __stwt(dst + lane + 3 * 32, v3);
        __stwt(dst + lane + 4 * 32, v4);
        __stwt(dst + lane + 5 * 32, v5);
    } else {
        const float4 z4 = make_float4(0.f, 0.f, 0.f, 0.f);
        #pragma unroll
        for (int i = 0; i < 6; i++)
            __stwt(dst + lane + i * 32, z4);
    }
}

// ---- fallback: single-kernel path (if M exceeds scratch) ------------------
__global__ __launch_bounds__(256) void k_direct(
    const float* __restrict__ query_pts,
    const float4* __restrict__ feats,
    const int*       __restrict__ table32,
    const long long* __restrict__ table64,
    float4* __restrict__ out,
    int M, int V)
{
    const int gwarp = (int)((blockIdx.x * blockDim.x + threadIdx.x) >> 5);
    const int lane  = threadIdx.x & 31;
    if (gwarp >= M) return;

    const float* qp = query_pts + 3ull * (unsigned)gwarp;
    int gx = __float2int_rd(__fdiv_rn(__ldg(qp + 0), 0.1f));
    int gy = __float2int_rd(__fdiv_rn(__ldg(qp + 1), 0.1f));
    int gz = __float2int_rd(__fdiv_rn(__ldg(qp + 2), 0.1f));
    unsigned h = ((unsigned)gx * 73856093u + (unsigned)gy * 19349669u
                + (unsigned)gz * 83492791u) & TABLE_MASK;

    long long vidx;
    if (g_table_is_i32) vidx = (long long)__ldg(table32 + h);
    else                vidx = __ldg(table64 + h);

    float4* dst = out + (size_t)gwarp * FDIM4;
    if (vidx >= 0 && vidx < (long long)V) {
        const float4* src = feats + (size_t)vidx * FDIM4;
        #pragma unroll
        for (int i = 0; i < 6; i++)
            __stwt(dst + lane + i * 32, __ldg(src + lane + i * 32));
    } else {
        const float4 z4 = make_float4(0.f, 0.f, 0.f, 0.f);
        #pragma unroll
        for (int i = 0; i < 6; i++)
            __stwt(dst + lane + i * 32, z4);
    }
}

extern "C" void kernel_launch(void* const* d_in, const int* in_sizes, int n_in,
                              void* d_out, int out_size)
{
    // ---- resolve input roles by element count ----
    int i_feat = 0;
    for (int i = 1; i < n_in; i++)
        if ((long long)in_sizes[i] > (long long)in_sizes[i_feat]) i_feat = i;

    int i_table = -1, i_query = -1;
    for (int i = 0; i < n_in; i++) {
        if (i == i_feat) continue;
        if (in_sizes[i] == (1 << 20)) i_table = i;
        else                          i_query = i;
    }
    if (i_table < 0 || i_query < 0) { i_query = 0; i_feat = 1; i_table = 2; }

    const float*     q     = (const float*)d_in[i_query];
    const float4*    feats = (const float4*)d_in[i_feat];
    const int*       t32   = (const int*)d_in[i_table];
    const long long* t64   = (const long long*)d_in[i_table];
    float4*          out   = (float4*)d_out;

    const int M = in_sizes[i_query] / 3;
    const int V = in_sizes[i_feat] / 768;

    k_init_detect<<<1, 1024>>>((const unsigned*)d_in[i_table]);

    if (M <= MAXM) {
        const int tpb = 256;
        k_pass1  <<<(M + tpb - 1) / tpb, tpb>>>(q, t32, t64, M, V);
        k_scan   <<<1, 1024>>>();
        k_scatter<<<(M + tpb - 1) / tpb, tpb>>>(M);
        const int blocks = (M * 32 + tpb - 1) / tpb;      // warp per query
        k_copy   <<<blocks, tpb>>>(feats, out, M);
    } else {
        const int blocks = (M * 32 + 255) / 256;
        k_direct<<<blocks, 256>>>(q, feats, t32, t64, out, M, V);
    }
}

// round 11
// speedup vs baseline: 1.0092x; 1.0027x over previous
#include <cuda_runtime.h>
#include <cstdint>

// VoxelHashTable: out[i] = voxel_features[table[hash(floor(q_i/0.1))]] or 0.
//
// R5: same two-phase clustering as R4 (bin queries by vidx>>7 so repeated /
// nearby rows hit L2 in the copy phase), but the scatter is now atomic-free:
// pass1 takes the per-bin rank (atomic folded into its memory-latency slack),
// scatter becomes a pure computed write. R4's k_scatter burned 18.7us on
// contended ATOMG latency (issue=1.1%).

#define FDIM4       192u            // 768/4 float4 per row
#define TABLE_MASK  0xFFFFFu        // 2^20 - 1
#define MAXM        (1 << 18)       // 262144 queries
#define NBINS       4096
#define BIN_SHIFT   7               // bin = vidx >> 7  (128 rows = 393KB per bin)

__device__ int g_table_is_i32;
__device__ int g_vidx[MAXM];        // per-query voxel index (-1 = invalid)
__device__ int g_rank[MAXM];        // per-query rank within its bin
__device__ int g_perm[MAXM];        // query ids sorted by bin
__device__ int g_hist[NBINS];
__device__ int g_offs[NBINS];

// ---- kernel 1: zero histogram + detect table dtype (1 block) --------------
// int64 table => every odd 32-bit word is 0x0 or 0xFFFFFFFF. int32 table =>
// ~24% of words are live indices, so 512 sampled words give certainty.
__global__ void k_init_detect(const unsigned* __restrict__ tbl_words)
{
    int t = threadIdx.x;                       // 1024 threads
    #pragma unroll
    for (int i = 0; i < NBINS / 1024; i++)
        g_hist[t + i * 1024] = 0;

    __shared__ int found;
    if (t == 0) found = 0;
    __syncthreads();
    if (t < 512) {
        unsigned w = tbl_words[2 * t + 1];
        if (w != 0u && w != 0xFFFFFFFFu) found = 1;
    }
    __syncthreads();
    if (t == 0) g_table_is_i32 = found;
}

// ---- kernel 2: hash + table lookup + histogram + per-bin rank -------------
__global__ __launch_bounds__(256) void k_pass1(
    const float* __restrict__ query_pts,
    const int*       __restrict__ table32,
    const long long* __restrict__ table64,
    int M, int V)
{
    int i = blockIdx.x * blockDim.x + threadIdx.x;
    if (i >= M) return;

    const float* qp = query_pts + 3ull * (unsigned)i;
    float x = __ldg(qp + 0);
    float y = __ldg(qp + 1);
    float z = __ldg(qp + 2);

    // bit-exact replica of jnp.floor(q / 0.1f): IEEE-RN fp32 division
    int gx = __float2int_rd(__fdiv_rn(x, 0.1f));
    int gy = __float2int_rd(__fdiv_rn(y, 0.1f));
    int gz = __float2int_rd(__fdiv_rn(z, 0.1f));

    // int64 (sum mod 2^20) == uint32 wraparound sum & (2^20-1): 2^20 | 2^32
    unsigned h = ((unsigned)gx * 73856093u
                + (unsigned)gy * 19349669u
                + (unsigned)gz * 83492791u) & TABLE_MASK;

    long long v;
    if (g_table_is_i32) v = (long long)__ldg(table32 + h);
    else                v = __ldg(table64 + h);

    int vidx = (v >= 0 && v < (long long)V) ? (int)v : -1;
    g_vidx[i] = vidx;

    int bin = (vidx < 0) ? 0 : (vidx >> BIN_SHIFT);
    // rank within bin; atomic latency hides behind this kernel's table/query
    // loads instead of standing alone like R4's scatter did.
    g_rank[i] = atomicAdd(&g_hist[bin], 1);
}

// ---- kernel 3: exclusive prefix scan over NBINS (1 block, 1024 thr) -------
__global__ void k_scan()
{
    __shared__ int s[1024];
    int t = threadIdx.x;
    const int PER = NBINS / 1024;              // 4

    int local[PER];
    int sum = 0;
    #pragma unroll
    for (int i = 0; i < PER; i++) { local[i] = g_hist[t * PER + i]; sum += local[i]; }
    s[t] = sum;
    __syncthreads();

    #pragma unroll
    for (int d = 1; d < 1024; d <<= 1) {
        int v = (t >= d) ? s[t - d] : 0;
        __syncthreads();
        s[t] += v;
        __syncthreads();
    }
    int base = s[t] - sum;                     // exclusive prefix of this thread
    #pragma unroll
    for (int i = 0; i < PER; i++) { g_offs[t * PER + i] = base; base += local[i]; }
}

// ---- kernel 4: atomic-free scatter ----------------------------------------
__global__ __launch_bounds__(256) void k_scatter(int M)
{
    int i = blockIdx.x * blockDim.x + threadIdx.x;
    if (i >= M) return;
    int vidx = g_vidx[i];
    int bin  = (vidx < 0) ? 0 : (vidx >> BIN_SHIFT);
    g_perm[g_offs[bin] + g_rank[i]] = i;
}

// ---- kernel 5: main copy, warp per query in clustered order ---------------
__global__ __launch_bounds__(256) void k_copy(
    const float4* __restrict__ feats,
    float4* __restrict__ out,
    int M)
{
    const int slot = (int)((blockIdx.x * blockDim.x + threadIdx.x) >> 5);
    const int lane = threadIdx.x & 31;
    if (slot >= M) return;

    const int qid  = g_perm[slot];
    const int vidx = g_vidx[qid];

    float4* dst = out + (size_t)(unsigned)qid * FDIM4;

    if (vidx >= 0) {
        const float4* src = feats + (size_t)(unsigned)vidx * FDIM4;
        float4 v0 = __ldg(src + lane + 0 * 32);
        float4 v1 = __ldg(src + lane + 1 * 32);
        float4 v2 = __ldg(src + lane + 2 * 32);
        float4 v3 = __ldg(src + lane + 3 * 32);
        float4 v4 = __ldg(src + lane + 4 * 32);
        float4 v5 = __ldg(src + lane + 5 * 32);
        __stwt(dst + lane + 0 * 32, v0);
        __stwt(dst + lane + 1 * 32, v1);
        __stwt(dst + lane + 2 * 32, v2);
        __stwt(dst + lane + 3 * 32, v3);
        __stwt(dst + lane + 4 * 32, v4);
        __stwt(dst + lane + 5 * 32, v5);
    } else {
        const float4 z4 = make_float4(0.f, 0.f, 0.f, 0.f);
        #pragma unroll
        for (int i = 0; i < 6; i++)
            __stwt(dst + lane + i * 32, z4);
    }
}

// ---- fallback: single-kernel path (if M exceeds scratch) ------------------
__global__ __launch_bounds__(256) void k_direct(
    const float* __restrict__ query_pts,
    const float4* __restrict__ feats,
    const int*       __restrict__ table32,
    const long long* __restrict__ table64,
    float4* __restrict__ out,
    int M, int V)
{
    const int gwarp = (int)((blockIdx.x * blockDim.x + threadIdx.x) >> 5);
    const int lane  = threadIdx.x & 31;
    if (gwarp >= M) return;

    const float* qp = query_pts + 3ull * (unsigned)gwarp;
    int gx = __float2int_rd(__fdiv_rn(__ldg(qp + 0), 0.1f));
    int gy = __float2int_rd(__fdiv_rn(__ldg(qp + 1), 0.1f));
    int gz = __float2int_rd(__fdiv_rn(__ldg(qp + 2), 0.1f));
    unsigned h = ((unsigned)gx * 73856093u + (unsigned)gy * 19349669u
                + (unsigned)gz * 83492791u) & TABLE_MASK;

    long long vidx;
    if (g_table_is_i32) vidx = (long long)__ldg(table32 + h);
    else                vidx = __ldg(table64 + h);

    float4* dst = out + (size_t)gwarp * FDIM4;
    if (vidx >= 0 && vidx < (long long)V) {
        const float4* src = feats + (size_t)vidx * FDIM4;
        #pragma unroll
        for (int i = 0; i < 6; i++)
            __stwt(dst + lane + i * 32, __ldg(src + lane + i * 32));
    } else {
        const float4 z4 = make_float4(0.f, 0.f, 0.f, 0.f);
        #pragma unroll
        for (int i = 0; i < 6; i++)
            __stwt(dst + lane + i * 32, z4);
    }
}

extern "C" void kernel_launch(void* const* d_in, const int* in_sizes, int n_in,
                              void* d_out, int out_size)
{
    // ---- resolve input roles by element count ----
    int i_feat = 0;
    for (int i = 1; i < n_in; i++)
        if ((long long)in_sizes[i] > (long long)in_sizes[i_feat]) i_feat = i;

    int i_table = -1, i_query = -1;
    for (int i = 0; i < n_in; i++) {
        if (i == i_feat) continue;
        if (in_sizes[i] == (1 << 20)) i_table = i;
        else                          i_query = i;
    }
    if (i_table < 0 || i_query < 0) { i_query = 0; i_feat = 1; i_table = 2; }

    const float*     q     = (const float*)d_in[i_query];
    const float4*    feats = (const float4*)d_in[i_feat];
    const int*       t32   = (const int*)d_in[i_table];
    const long long* t64   = (const long long*)d_in[i_table];
    float4*          out   = (float4*)d_out;

    const int M = in_sizes[i_query] / 3;
    const int V = in_sizes[i_feat] / 768;

    k_init_detect<<<1, 1024>>>((const unsigned*)d_in[i_table]);

    if (M <= MAXM) {
        const int tpb = 256;
        k_pass1  <<<(M + tpb - 1) / tpb, tpb>>>(q, t32, t64, M, V);
        k_scan   <<<1, 1024>>>();
        k_scatter<<<(M + tpb - 1) / tpb, tpb>>>(M);
        const int blocks = (M * 32 + tpb - 1) / tpb;      // warp per query
        k_copy   <<<blocks, tpb>>>(feats, out, M);
    } else {
        const int blocks = (M * 32 + 255) / 256;
        k_direct<<<blocks, 256>>>(q, feats, t32, t64, out, M, V);
    }
}